// round 9
// baseline (speedup 1.0000x reference)
#include <cuda_runtime.h>
#include <cstdint>

#define NMAX 50000
#define EMAX 800000
#define NEG_INF __int_as_float(0xff800000)

// ---------------- scratch (device globals; aligned for float4 access) -------
__device__ __align__(256) float g_h1[NMAX * 128];    // layer1 features [N,2,64]
__device__ __align__(256) float g_agg1[NMAX * 128];  // layer1 agg out (layer2 input)
__device__ __align__(256) float g_h2[NMAX * 64];     // layer2 features [N,2,32]
__device__ __align__(256) float g_agg2[NMAX * 64];   // layer2 agg out
__device__ __align__(256) float g_asrc1[NMAX * 2], g_adst1[NMAX * 2];
__device__ __align__(256) float g_max1[NMAX * 2],  g_sum1[NMAX * 2];
__device__ __align__(256) float g_asrc2[NMAX * 2], g_adst2[NMAX * 2];
__device__ __align__(256) float g_max2[NMAX * 2],  g_sum2[NMAX * 2];

// ---------------- helpers ----------------------------------------------------
__device__ __forceinline__ float lrelu(float x) { return x > 0.f ? x : 0.2f * x; }

__device__ __forceinline__ void atomicMaxFloat(float* addr, float value) {
    if (value >= 0.f)
        atomicMax((int*)addr, __float_as_int(value));
    else
        atomicMin((unsigned int*)addr, __float_as_uint(value));
}

// ---------------- GEMM: C[n,j] = sum_k A[n,k] * W[k,j], K = 128 --------------
// LAYER 0: A = x (param), C = g_h1, J = 128.
// LAYER 1: A = g_agg1,    C = g_h2, J = 64.
template <int J, int LAYER>
__global__ void gemm_kernel(const float* __restrict__ A_param, const float* __restrict__ W,
                            int n_rows) {
    constexpr int COLT = J / 4;        // threads along columns (float4 each)
    constexpr int RPT  = 64 / (256 / COLT);  // rows per thread

    __shared__ float x_sm[64][36];     // 64 rows x 32 k (pad 4)
    __shared__ float w_sm[32][J];      // one K-tile of W

    const float* A = (LAYER == 1) ? (const float*)g_agg1 : A_param;
    float*       C = (LAYER == 1) ? g_h2 : g_h1;

    const int row0 = blockIdx.x * 64;
    const int tid  = threadIdx.x;
    const int tj   = tid % COLT;
    const int tn   = tid / COLT;

    float acc[RPT][4];
#pragma unroll
    for (int i = 0; i < RPT; i++) { acc[i][0] = acc[i][1] = acc[i][2] = acc[i][3] = 0.f; }

    for (int kt = 0; kt < 128; kt += 32) {
        __syncthreads();
        // load x tile: 64 rows x 8 float4 = 512 float4, 2 per thread
#pragma unroll
        for (int l = 0; l < 2; l++) {
            int i = tid + l * 256;
            int r = i >> 3, c4 = i & 7;
            float4 v = make_float4(0.f, 0.f, 0.f, 0.f);
            if (row0 + r < n_rows)
                v = *(const float4*)&A[(size_t)(row0 + r) * 128 + kt + c4 * 4];
            x_sm[r][c4 * 4 + 0] = v.x;
            x_sm[r][c4 * 4 + 1] = v.y;
            x_sm[r][c4 * 4 + 2] = v.z;
            x_sm[r][c4 * 4 + 3] = v.w;
        }
        // load w tile: 32 x (J/4) float4
#pragma unroll
        for (int i = tid; i < 32 * (J / 4); i += 256) {
            int r = i / (J / 4), c4 = i % (J / 4);
            *(float4*)&w_sm[r][c4 * 4] = *(const float4*)&W[(size_t)(kt + r) * J + c4 * 4];
        }
        __syncthreads();
#pragma unroll
        for (int k = 0; k < 32; k++) {
            float4 w = *(float4*)&w_sm[k][tj * 4];
#pragma unroll
            for (int i = 0; i < RPT; i++) {
                float xv = x_sm[tn * RPT + i][k];
                acc[i][0] += xv * w.x;
                acc[i][1] += xv * w.y;
                acc[i][2] += xv * w.z;
                acc[i][3] += xv * w.w;
            }
        }
    }

#pragma unroll
    for (int i = 0; i < RPT; i++) {
        int r = row0 + tn * RPT + i;
        if (r < n_rows)
            *(float4*)&C[(size_t)r * J + tj * 4] =
                make_float4(acc[i][0], acc[i][1], acc[i][2], acc[i][3]);
    }
}

// ---------------- attention projections: a[n,h] = dot(h[n,h,:], att[h,:]) ----
template <int C, int LAYER>
__global__ void attn_proj_kernel(const float* __restrict__ att_src,
                                 const float* __restrict__ att_dst, int n) {
    const float* h     = (LAYER == 0) ? (const float*)g_h1 : (const float*)g_h2;
    float*       a_src = (LAYER == 0) ? g_asrc1 : g_asrc2;
    float*       a_dst = (LAYER == 0) ? g_adst1 : g_adst2;

    int warp = (blockIdx.x * blockDim.x + threadIdx.x) >> 5;
    int lane = threadIdx.x & 31;
    if (warp >= n) return;
    const float* row = h + (size_t)warp * (2 * C);
    float s0 = 0.f, s1 = 0.f, d0 = 0.f, d1 = 0.f;
    for (int c = lane; c < C; c += 32) {
        float h0 = row[c], h1v = row[C + c];
        s0 += h0 * att_src[c];
        s1 += h1v * att_src[C + c];
        d0 += h0 * att_dst[c];
        d1 += h1v * att_dst[C + c];
    }
#pragma unroll
    for (int o = 16; o > 0; o >>= 1) {
        s0 += __shfl_down_sync(0xffffffffu, s0, o);
        s1 += __shfl_down_sync(0xffffffffu, s1, o);
        d0 += __shfl_down_sync(0xffffffffu, d0, o);
        d1 += __shfl_down_sync(0xffffffffu, d1, o);
    }
    if (lane == 0) {
        a_src[warp * 2]     = s0;
        a_src[warp * 2 + 1] = s1;
        a_dst[warp * 2]     = d0;
        a_dst[warp * 2 + 1] = d1;
    }
}

// ---------------- init (max = -inf, sum = 0, agg = 0) ------------------------
template <int LAYER>
__global__ void init_kernel(int n2, int nagg) {
    float* mx  = (LAYER == 0) ? g_max1 : g_max2;
    float* sum = (LAYER == 0) ? g_sum1 : g_sum2;
    float* agg = (LAYER == 0) ? g_agg1 : g_agg2;
    for (int i = blockIdx.x * blockDim.x + threadIdx.x; i < nagg; i += gridDim.x * blockDim.x) {
        agg[i] = 0.f;
        if (i < n2) {
            mx[i]  = NEG_INF;
            sum[i] = 0.f;
        }
    }
}

// ---------------- edge pass 1: segment max -----------------------------------
template <int LAYER>
__global__ void edge_max_kernel(const int* __restrict__ ei, int E, int n) {
    const float* a_src = (LAYER == 0) ? g_asrc1 : g_asrc2;
    const float* a_dst = (LAYER == 0) ? g_adst1 : g_adst2;
    float*       mx    = (LAYER == 0) ? g_max1  : g_max2;

    int i = blockIdx.x * blockDim.x + threadIdx.x;
    if (i >= E + n) return;
    int s, d;
    if (i < E) { s = ei[i]; d = ei[E + i]; } else { s = d = i - E; }
    float2 as = ((const float2*)a_src)[s];
    float2 ad = ((const float2*)a_dst)[d];
    atomicMaxFloat(&mx[d * 2],     lrelu(as.x + ad.x));
    atomicMaxFloat(&mx[d * 2 + 1], lrelu(as.y + ad.y));
}

// ---------------- edge pass 2: segment sum of exp ----------------------------
template <int LAYER>
__global__ void edge_sum_kernel(const int* __restrict__ ei, int E, int n) {
    const float* a_src = (LAYER == 0) ? g_asrc1 : g_asrc2;
    const float* a_dst = (LAYER == 0) ? g_adst1 : g_adst2;
    const float* mx    = (LAYER == 0) ? g_max1  : g_max2;
    float*       sum   = (LAYER == 0) ? g_sum1  : g_sum2;

    int i = blockIdx.x * blockDim.x + threadIdx.x;
    if (i >= E + n) return;
    int s, d;
    if (i < E) { s = ei[i]; d = ei[E + i]; } else { s = d = i - E; }
    float2 as = ((const float2*)a_src)[s];
    float2 ad = ((const float2*)a_dst)[d];
    float2 m  = ((const float2*)mx)[d];
    atomicAdd(&sum[d * 2],     __expf(lrelu(as.x + ad.x) - m.x));
    atomicAdd(&sum[d * 2 + 1], __expf(lrelu(as.y + ad.y) - m.y));
}

// ---------------- edge pass 3: weighted aggregation --------------------------
// HC = feature width (128 for layer1, 64 for layer2). LPE lanes per edge = HC/4.
template <int HC, int LAYER>
__global__ void aggregate_kernel(const int* __restrict__ ei, int E, int n) {
    const float* a_src = (LAYER == 0) ? g_asrc1 : g_asrc2;
    const float* a_dst = (LAYER == 0) ? g_adst1 : g_adst2;
    const float* mx    = (LAYER == 0) ? g_max1  : g_max2;
    const float* sum   = (LAYER == 0) ? g_sum1  : g_sum2;
    const float* h     = (LAYER == 0) ? (const float*)g_h1  : (const float*)g_h2;
    float*       agg   = (LAYER == 0) ? g_agg1 : g_agg2;

    constexpr int LPE = HC / 4;  // lanes per edge (float4 each)
    int gid  = blockIdx.x * blockDim.x + threadIdx.x;
    int edge = gid / LPE;
    int lane = gid % LPE;
    if (edge >= E + n) return;
    int s, d;
    if (edge < E) { s = ei[edge]; d = ei[E + edge]; } else { s = d = edge - E; }
    float2 as = ((const float2*)a_src)[s];
    float2 ad = ((const float2*)a_dst)[d];
    float2 m  = ((const float2*)mx)[d];
    float2 ss = ((const float2*)sum)[d];
    float al0 = __expf(lrelu(as.x + ad.x) - m.x) / (ss.x + 1e-16f);
    float al1 = __expf(lrelu(as.y + ad.y) - m.y) / (ss.y + 1e-16f);
    float4 hv = ((const float4*)(h + (size_t)s * HC))[lane];
    float a = (lane < LPE / 2) ? al0 : al1;
    float* dst = agg + (size_t)d * HC + lane * 4;
    atomicAdd(dst + 0, hv.x * a);
    atomicAdd(dst + 1, hv.y * a);
    atomicAdd(dst + 2, hv.z * a);
    atomicAdd(dst + 3, hv.w * a);
}

// ---------------- bias + relu (in place, layer1) -----------------------------
__global__ void bias_relu_kernel(const float* __restrict__ bias, int total) {
    int i = blockIdx.x * blockDim.x + threadIdx.x;
    if (i >= total) return;
    float v = g_agg1[i] + bias[i & 127];
    g_agg1[i] = v > 0.f ? v : 0.f;
}

// ---------------- finalize: mean over heads + bias ---------------------------
__global__ void finalize_kernel(const float* __restrict__ bias, float* __restrict__ out, int n) {
    int i = blockIdx.x * blockDim.x + threadIdx.x;
    if (i >= n * 32) return;
    int node = i >> 5, c = i & 31;
    out[i] = 0.5f * (g_agg2[node * 64 + c] + g_agg2[node * 64 + 32 + c]) + bias[c];
}

// ---------------- launch -----------------------------------------------------
extern "C" void kernel_launch(void* const* d_in, const int* in_sizes, int n_in,
                              void* d_out, int out_size) {
    const float* x   = (const float*)d_in[0];
    const int*   ei  = (const int*)d_in[1];     // int32 on device (JAX x64 disabled)
    const float* W1  = (const float*)d_in[2];
    const float* as1 = (const float*)d_in[3];
    const float* ad1 = (const float*)d_in[4];
    const float* b1  = (const float*)d_in[5];
    const float* W2  = (const float*)d_in[6];
    const float* as2 = (const float*)d_in[7];
    const float* ad2 = (const float*)d_in[8];
    const float* b2  = (const float*)d_in[9];
    float*       out = (float*)d_out;

    const int N  = in_sizes[0] / 128;
    const int E  = in_sizes[1] / 2;
    const int EN = E + N;

    const int nb_gemm = (N + 63) / 64;
    const int nb_warp = (N * 32 + 255) / 256;
    const int nb_edge = (EN + 255) / 256;

    // ===== Layer 1 =====
    gemm_kernel<128, 0><<<nb_gemm, 256>>>(x, W1, N);
    attn_proj_kernel<64, 0><<<nb_warp, 256>>>(as1, ad1, N);
    init_kernel<0><<<1024, 256>>>(N * 2, N * 128);
    edge_max_kernel<0><<<nb_edge, 256>>>(ei, E, N);
    edge_sum_kernel<0><<<nb_edge, 256>>>(ei, E, N);
    aggregate_kernel<128, 0><<<((size_t)EN * 32 + 255) / 256, 256>>>(ei, E, N);
    bias_relu_kernel<<<(N * 128 + 255) / 256, 256>>>(b1, N * 128);

    // ===== Layer 2 =====
    gemm_kernel<64, 1><<<nb_gemm, 256>>>(nullptr, W2, N);
    attn_proj_kernel<32, 1><<<nb_warp, 256>>>(as2, ad2, N);
    init_kernel<1><<<1024, 256>>>(N * 2, N * 64);
    edge_max_kernel<1><<<nb_edge, 256>>>(ei, E, N);
    edge_sum_kernel<1><<<nb_edge, 256>>>(ei, E, N);
    aggregate_kernel<64, 1><<<((size_t)EN * 16 + 255) / 256, 256>>>(ei, E, N);
    finalize_kernel<<<(N * 32 + 255) / 256, 256>>>(b2, out, N);
}

// round 12
// speedup vs baseline: 2.0447x; 2.0447x over previous
#include <cuda_runtime.h>
#include <cstdint>

#define NMAX 50000
#define EMAX 800000

// ---------------- scratch (device globals) -----------------------------------
__device__ __align__(256) float g_h1[NMAX * 128];    // layer1 features [N,2,64]
__device__ __align__(256) float g_agg1[NMAX * 128];  // layer1 out = layer2 input
__device__ __align__(256) float g_h2[NMAX * 64];     // layer2 features [N,2,32]
__device__ __align__(256) float g_asrc1[NMAX * 2], g_adst1[NMAX * 2];
__device__ __align__(256) float g_asrc2[NMAX * 2], g_adst2[NMAX * 2];
__device__ __align__(256) int   g_cnt[NMAX];         // in-degree counts
__device__ __align__(256) int   g_cur[NMAX];         // scatter cursors
__device__ __align__(256) int   g_ptr[NMAX + 1];     // CSR row pointers
__device__ __align__(256) int   g_csr[EMAX];         // CSR column (source) ids

// ---------------- helpers ----------------------------------------------------
__device__ __forceinline__ float lrelu(float x) { return x > 0.f ? x : 0.2f * x; }

// ---------------- CSR build --------------------------------------------------
__global__ void zero_kernel(int n) {
    int i = blockIdx.x * blockDim.x + threadIdx.x;
    if (i < n) { g_cnt[i] = 0; g_cur[i] = 0; }
}

__global__ void count_kernel(const int* __restrict__ ei, int E) {
    int i = blockIdx.x * blockDim.x + threadIdx.x;
    if (i < E) atomicAdd(&g_cnt[ei[E + i]], 1);
}

// single-block exclusive scan of g_cnt[0..n) -> g_ptr
__global__ void scan_kernel(int n) {
    __shared__ int sm[1024];
    const int tid = threadIdx.x;
    int carry = 0;
    if (tid == 0) g_ptr[0] = 0;
    for (int base = 0; base < n; base += 1024) {
        int i = base + tid;
        int v = (i < n) ? g_cnt[i] : 0;
        sm[tid] = v;
        __syncthreads();
#pragma unroll
        for (int off = 1; off < 1024; off <<= 1) {
            int t = (tid >= off) ? sm[tid - off] : 0;
            __syncthreads();
            sm[tid] += t;
            __syncthreads();
        }
        if (i < n) g_ptr[i + 1] = carry + sm[tid];
        int tot = sm[1023];
        __syncthreads();
        carry += tot;
    }
}

__global__ void scatter_kernel(const int* __restrict__ ei, int E) {
    int i = blockIdx.x * blockDim.x + threadIdx.x;
    if (i >= E) return;
    int s = ei[i], d = ei[E + i];
    int pos = atomicAdd(&g_cur[d], 1);
    g_csr[g_ptr[d] + pos] = s;
}

// ---------------- GEMM: C[n,j] = sum_k A[n,k] * W[k,j], K = 128 --------------
// LAYER 0: A = x (param), C = g_h1, J = 128.  LAYER 1: A = g_agg1, C = g_h2, J = 64.
template <int J, int LAYER>
__global__ void gemm_kernel(const float* __restrict__ A_param, const float* __restrict__ W,
                            int n_rows) {
    constexpr int COLT = J / 4;
    constexpr int RPT  = 64 / (256 / COLT);

    __shared__ float x_sm[64][36];
    __shared__ float w_sm[32][J];

    const float* A = (LAYER == 1) ? (const float*)g_agg1 : A_param;
    float*       C = (LAYER == 1) ? g_h2 : g_h1;

    const int row0 = blockIdx.x * 64;
    const int tid  = threadIdx.x;
    const int tj   = tid % COLT;
    const int tn   = tid / COLT;

    float acc[RPT][4];
#pragma unroll
    for (int i = 0; i < RPT; i++) { acc[i][0] = acc[i][1] = acc[i][2] = acc[i][3] = 0.f; }

    for (int kt = 0; kt < 128; kt += 32) {
        __syncthreads();
#pragma unroll
        for (int l = 0; l < 2; l++) {
            int i = tid + l * 256;
            int r = i >> 3, c4 = i & 7;
            float4 v = make_float4(0.f, 0.f, 0.f, 0.f);
            if (row0 + r < n_rows)
                v = *(const float4*)&A[(size_t)(row0 + r) * 128 + kt + c4 * 4];
            x_sm[r][c4 * 4 + 0] = v.x;
            x_sm[r][c4 * 4 + 1] = v.y;
            x_sm[r][c4 * 4 + 2] = v.z;
            x_sm[r][c4 * 4 + 3] = v.w;
        }
#pragma unroll
        for (int i = tid; i < 32 * (J / 4); i += 256) {
            int r = i / (J / 4), c4 = i % (J / 4);
            *(float4*)&w_sm[r][c4 * 4] = *(const float4*)&W[(size_t)(kt + r) * J + c4 * 4];
        }
        __syncthreads();
#pragma unroll
        for (int k = 0; k < 32; k++) {
            float4 w = *(float4*)&w_sm[k][tj * 4];
#pragma unroll
            for (int i = 0; i < RPT; i++) {
                float xv = x_sm[tn * RPT + i][k];
                acc[i][0] += xv * w.x;
                acc[i][1] += xv * w.y;
                acc[i][2] += xv * w.z;
                acc[i][3] += xv * w.w;
            }
        }
    }

#pragma unroll
    for (int i = 0; i < RPT; i++) {
        int r = row0 + tn * RPT + i;
        if (r < n_rows)
            *(float4*)&C[(size_t)r * J + tj * 4] =
                make_float4(acc[i][0], acc[i][1], acc[i][2], acc[i][3]);
    }
}

// ---------------- attention projections --------------------------------------
template <int C, int LAYER>
__global__ void attn_proj_kernel(const float* __restrict__ att_src,
                                 const float* __restrict__ att_dst, int n) {
    const float* h     = (LAYER == 0) ? (const float*)g_h1 : (const float*)g_h2;
    float*       a_src = (LAYER == 0) ? g_asrc1 : g_asrc2;
    float*       a_dst = (LAYER == 0) ? g_adst1 : g_adst2;

    int warp = (blockIdx.x * blockDim.x + threadIdx.x) >> 5;
    int lane = threadIdx.x & 31;
    if (warp >= n) return;
    const float* row = h + (size_t)warp * (2 * C);
    float s0 = 0.f, s1 = 0.f, d0 = 0.f, d1 = 0.f;
    for (int c = lane; c < C; c += 32) {
        float h0 = row[c], h1v = row[C + c];
        s0 += h0 * att_src[c];
        s1 += h1v * att_src[C + c];
        d0 += h0 * att_dst[c];
        d1 += h1v * att_dst[C + c];
    }
#pragma unroll
    for (int o = 16; o > 0; o >>= 1) {
        s0 += __shfl_down_sync(0xffffffffu, s0, o);
        s1 += __shfl_down_sync(0xffffffffu, s1, o);
        d0 += __shfl_down_sync(0xffffffffu, d0, o);
        d1 += __shfl_down_sync(0xffffffffu, d1, o);
    }
    if (lane == 0) {
        a_src[warp * 2]     = s0;
        a_src[warp * 2 + 1] = s1;
        a_dst[warp * 2]     = d0;
        a_dst[warp * 2 + 1] = d1;
    }
}

// ---------------- fused GAT layer: softmax + aggregate + epilogue ------------
// One warp per destination node. HC = 128 (layer1) or 64 (layer2).
template <int HC, int LAYER>
__global__ void gat_fused_kernel(const float* __restrict__ bias,
                                 float* __restrict__ out, int n) {
    const float* asrc = (LAYER == 0) ? g_asrc1 : g_asrc2;
    const float* adst = (LAYER == 0) ? g_adst1 : g_adst2;
    const float* h    = (LAYER == 0) ? (const float*)g_h1 : (const float*)g_h2;

    const int d    = (blockIdx.x * blockDim.x + threadIdx.x) >> 5;
    const int lane = threadIdx.x & 31;
    if (d >= n) return;

    const int p0 = g_ptr[d], p1 = g_ptr[d + 1];
    const float2 ad    = ((const float2*)adst)[d];
    const float2 aself = ((const float2*)asrc)[d];
    const float e0s = lrelu(aself.x + ad.x);
    const float e1s = lrelu(aself.y + ad.y);

    // ---- phase 1: max (self loop included) ----
    float m0 = e0s, m1 = e1s;
    for (int i = p0 + lane; i < p1; i += 32) {
        int s = g_csr[i];
        float2 as = ((const float2*)asrc)[s];
        m0 = fmaxf(m0, lrelu(as.x + ad.x));
        m1 = fmaxf(m1, lrelu(as.y + ad.y));
    }
#pragma unroll
    for (int o = 16; o > 0; o >>= 1) {
        m0 = fmaxf(m0, __shfl_xor_sync(0xffffffffu, m0, o));
        m1 = fmaxf(m1, __shfl_xor_sync(0xffffffffu, m1, o));
    }

    // ---- phase 2: sum of exp ----
    float s0 = 0.f, s1 = 0.f;
    for (int i = p0 + lane; i < p1; i += 32) {
        int s = g_csr[i];
        float2 as = ((const float2*)asrc)[s];
        s0 += __expf(lrelu(as.x + ad.x) - m0);
        s1 += __expf(lrelu(as.y + ad.y) - m1);
    }
#pragma unroll
    for (int o = 16; o > 0; o >>= 1) {
        s0 += __shfl_xor_sync(0xffffffffu, s0, o);
        s1 += __shfl_xor_sync(0xffffffffu, s1, o);
    }
    s0 += __expf(e0s - m0);
    s1 += __expf(e1s - m1);
    const float inv0 = 1.f / (s0 + 1e-16f);
    const float inv1 = 1.f / (s1 + 1e-16f);

    // head-selected constants for phase 3 (half-warp per head)
    const bool  h0lane = (lane < 16);
    const float adH  = h0lane ? ad.x : ad.y;
    const float mH   = h0lane ? m0 : m1;
    const float invH = h0lane ? inv0 : inv1;

    if (HC == 128) {
        // 32 lanes x float4 = 128 cols; lanes 0-15 head0, 16-31 head1
        float4 acc = make_float4(0.f, 0.f, 0.f, 0.f);
        for (int i = p0; i < p1; i++) {
            int s = g_csr[i];
            const float2 as = ((const float2*)asrc)[s];
            float aH = h0lane ? as.x : as.y;
            float al = __expf(lrelu(aH + adH) - mH) * invH;
            float4 hv = *(const float4*)&h[(size_t)s * 128 + lane * 4];
            acc.x += al * hv.x; acc.y += al * hv.y;
            acc.z += al * hv.z; acc.w += al * hv.w;
        }
        {   // self loop
            float aH = h0lane ? aself.x : aself.y;
            float al = __expf(lrelu(aH + adH) - mH) * invH;
            float4 hv = *(const float4*)&h[(size_t)d * 128 + lane * 4];
            acc.x += al * hv.x; acc.y += al * hv.y;
            acc.z += al * hv.z; acc.w += al * hv.w;
        }
        float4 b = *(const float4*)&bias[lane * 4];
        acc.x = fmaxf(acc.x + b.x, 0.f);
        acc.y = fmaxf(acc.y + b.y, 0.f);
        acc.z = fmaxf(acc.z + b.z, 0.f);
        acc.w = fmaxf(acc.w + b.w, 0.f);
        *(float4*)&g_agg1[(size_t)d * 128 + lane * 4] = acc;
    } else {
        // HC = 64: 32 lanes x float2; lanes 0-15 head0, 16-31 head1
        float2 acc = make_float2(0.f, 0.f);
        for (int i = p0; i < p1; i++) {
            int s = g_csr[i];
            const float2 as = ((const float2*)asrc)[s];
            float aH = h0lane ? as.x : as.y;
            float al = __expf(lrelu(aH + adH) - mH) * invH;
            float2 hv = *(const float2*)&h[(size_t)s * 64 + lane * 2];
            acc.x += al * hv.x; acc.y += al * hv.y;
        }
        {   // self loop
            float aH = h0lane ? aself.x : aself.y;
            float al = __expf(lrelu(aH + adH) - mH) * invH;
            float2 hv = *(const float2*)&h[(size_t)d * 64 + lane * 2];
            acc.x += al * hv.x; acc.y += al * hv.y;
        }
        // mean over heads: lane L (head0 cols 2L,2L+1) pairs with lane L+16
        float ox = __shfl_xor_sync(0xffffffffu, acc.x, 16);
        float oy = __shfl_xor_sync(0xffffffffu, acc.y, 16);
        if (lane < 16) {
            float2 o;
            o.x = 0.5f * (acc.x + ox) + bias[lane * 2];
            o.y = 0.5f * (acc.y + oy) + bias[lane * 2 + 1];
            *(float2*)&out[(size_t)d * 32 + lane * 2] = o;
        }
    }
}

// ---------------- launch -----------------------------------------------------
extern "C" void kernel_launch(void* const* d_in, const int* in_sizes, int n_in,
                              void* d_out, int out_size) {
    const float* x   = (const float*)d_in[0];
    const int*   ei  = (const int*)d_in[1];
    const float* W1  = (const float*)d_in[2];
    const float* as1 = (const float*)d_in[3];
    const float* ad1 = (const float*)d_in[4];
    const float* b1  = (const float*)d_in[5];
    const float* W2  = (const float*)d_in[6];
    const float* as2 = (const float*)d_in[7];
    const float* ad2 = (const float*)d_in[8];
    const float* b2  = (const float*)d_in[9];
    float*       out = (float*)d_out;

    const int N = in_sizes[0] / 128;
    const int E = in_sizes[1] / 2;

    const int nb_gemm = (N + 63) / 64;
    const int nb_warp = (N * 32 + 255) / 256;

    // CSR build (edge list is identical for both layers)
    zero_kernel<<<(N + 255) / 256, 256>>>(N);
    count_kernel<<<(E + 255) / 256, 256>>>(ei, E);
    scan_kernel<<<1, 1024>>>(N);
    scatter_kernel<<<(E + 255) / 256, 256>>>(ei, E);

    // ===== Layer 1 =====
    gemm_kernel<128, 0><<<nb_gemm, 256>>>(x, W1, N);
    attn_proj_kernel<64, 0><<<nb_warp, 256>>>(as1, ad1, N);
    gat_fused_kernel<128, 0><<<nb_warp, 256>>>(b1, nullptr, N);

    // ===== Layer 2 =====
    gemm_kernel<64, 1><<<nb_gemm, 256>>>(nullptr, W2, N);
    attn_proj_kernel<32, 1><<<nb_warp, 256>>>(as2, ad2, N);
    gat_fused_kernel<64, 1><<<nb_warp, 256>>>(b2, out, N);
}

// round 14
// speedup vs baseline: 2.9373x; 1.4365x over previous
#include <cuda_runtime.h>
#include <cstdint>

#define NMAX 50000
#define EMAX 800000

// ---------------- scratch (device globals) -----------------------------------
__device__ __align__(256) float g_h1[NMAX * 128];    // layer1 features [N,2,64]
__device__ __align__(256) float g_agg1[NMAX * 128];  // layer1 out = layer2 input
__device__ __align__(256) float g_h2[NMAX * 64];     // layer2 features [N,2,32]
__device__ __align__(256) float g_asrc1[NMAX * 2], g_adst1[NMAX * 2];
__device__ __align__(256) float g_asrc2[NMAX * 2], g_adst2[NMAX * 2];
__device__ __align__(256) int   g_cnt[NMAX];         // in-degree counts / cursors
__device__ __align__(256) int   g_ptr[NMAX + 1];     // CSR row pointers
__device__ __align__(256) int   g_csr[EMAX];         // CSR source ids

// ---------------- helpers ----------------------------------------------------
__device__ __forceinline__ float lrelu(float x) { return x > 0.f ? x : 0.2f * x; }

// ---------------- CSR build --------------------------------------------------
__global__ void zero_kernel(int n) {
    int i = blockIdx.x * blockDim.x + threadIdx.x;
    if (i < n) g_cnt[i] = 0;
}

__global__ void count_kernel(const int* __restrict__ ei, int E) {
    int i = blockIdx.x * blockDim.x + threadIdx.x;
    if (i < E) atomicAdd(&g_cnt[ei[E + i]], 1);
}

// single-block exclusive scan of g_cnt[0..n) -> g_ptr (shfl-based)
__global__ void scan_kernel(int n) {
    __shared__ int warp_off[32];
    __shared__ int carry_sm;
    const int tid = threadIdx.x, lane = tid & 31, wid = tid >> 5;
    if (tid == 0) { g_ptr[0] = 0; carry_sm = 0; }
    __syncthreads();
    for (int base = 0; base < n; base += 1024) {
        int i = base + tid;
        int v = (i < n) ? g_cnt[i] : 0;
        int x = v;
#pragma unroll
        for (int o = 1; o < 32; o <<= 1) {
            int t = __shfl_up_sync(0xffffffffu, x, o);
            if (lane >= o) x += t;
        }
        if (lane == 31) warp_off[wid] = x;
        __syncthreads();
        if (wid == 0) {
            int w = warp_off[lane];
            int y = w;
#pragma unroll
            for (int o = 1; o < 32; o <<= 1) {
                int t = __shfl_up_sync(0xffffffffu, y, o);
                if (lane >= o) y += t;
            }
            warp_off[lane] = y - w;  // exclusive offsets
        }
        __syncthreads();
        int incl = x + warp_off[wid] + carry_sm;
        if (i < n) g_ptr[i + 1] = incl;
        __syncthreads();
        if (tid == 1023) carry_sm = incl;
        __syncthreads();
    }
}

// scatter with atomicSub on counts (cursor-free; leaves g_cnt at 0)
__global__ void scatter_kernel(const int* __restrict__ ei, int E) {
    int i = blockIdx.x * blockDim.x + threadIdx.x;
    if (i >= E) return;
    int s = ei[i], d = ei[E + i];
    int pos = atomicSub(&g_cnt[d], 1) - 1;
    g_csr[g_ptr[d] + pos] = s;
}

// ---------------- GEMM + fused attention projections -------------------------
// C[n,j] = sum_k A[n,k]*W[k,j]; epilogue computes a_src/a_dst per node+head.
// LAYER 0: A = x (param), C = g_h1, J = 128.  LAYER 1: A = g_agg1, C = g_h2, J = 64.
template <int J, int LAYER>
__global__ void gemm_kernel(const float* __restrict__ A_param, const float* __restrict__ W,
                            const float* __restrict__ att_src, const float* __restrict__ att_dst,
                            int n_rows) {
    constexpr int COLT = J / 4;               // threads across columns
    constexpr int RPT  = 64 / (256 / COLT);   // rows per thread
    constexpr int HL   = COLT / 2;            // lanes per head within a row group

    __shared__ float x_sm[64][36];
    __shared__ float w_sm[32][J];

    const float* A     = (LAYER == 1) ? (const float*)g_agg1 : A_param;
    float*       C     = (LAYER == 1) ? g_h2 : g_h1;
    float*       a_src = (LAYER == 0) ? g_asrc1 : g_asrc2;
    float*       a_dst = (LAYER == 0) ? g_adst1 : g_adst2;

    const int row0 = blockIdx.x * 64;
    const int tid  = threadIdx.x;
    const int tj   = tid % COLT;
    const int tn   = tid / COLT;
    const int lane = tid & 31;

    float acc[RPT][4];
#pragma unroll
    for (int i = 0; i < RPT; i++) { acc[i][0] = acc[i][1] = acc[i][2] = acc[i][3] = 0.f; }

    for (int kt = 0; kt < 128; kt += 32) {
        __syncthreads();
#pragma unroll
        for (int l = 0; l < 2; l++) {
            int i = tid + l * 256;
            int r = i >> 3, c4 = i & 7;
            float4 v = make_float4(0.f, 0.f, 0.f, 0.f);
            if (row0 + r < n_rows)
                v = *(const float4*)&A[(size_t)(row0 + r) * 128 + kt + c4 * 4];
            x_sm[r][c4 * 4 + 0] = v.x;
            x_sm[r][c4 * 4 + 1] = v.y;
            x_sm[r][c4 * 4 + 2] = v.z;
            x_sm[r][c4 * 4 + 3] = v.w;
        }
#pragma unroll
        for (int i = tid; i < 32 * (J / 4); i += 256) {
            int r = i / (J / 4), c4 = i % (J / 4);
            *(float4*)&w_sm[r][c4 * 4] = *(const float4*)&W[(size_t)(kt + r) * J + c4 * 4];
        }
        __syncthreads();
#pragma unroll
        for (int k = 0; k < 32; k++) {
            float4 w = *(float4*)&w_sm[k][tj * 4];
#pragma unroll
            for (int i = 0; i < RPT; i++) {
                float xv = x_sm[tn * RPT + i][k];
                acc[i][0] += xv * w.x;
                acc[i][1] += xv * w.y;
                acc[i][2] += xv * w.z;
                acc[i][3] += xv * w.w;
            }
        }
    }

    // att weights for this thread's 4 columns
    const float4 avs = *(const float4*)&att_src[tj * 4];
    const float4 avd = *(const float4*)&att_dst[tj * 4];

#pragma unroll
    for (int i = 0; i < RPT; i++) {
        int r = row0 + tn * RPT + i;
        if (r < n_rows) {
            *(float4*)&C[(size_t)r * J + tj * 4] =
                make_float4(acc[i][0], acc[i][1], acc[i][2], acc[i][3]);
            // attention partials: reduce over the HL lanes of this head
            float ps = acc[i][0] * avs.x + acc[i][1] * avs.y + acc[i][2] * avs.z + acc[i][3] * avs.w;
            float pd = acc[i][0] * avd.x + acc[i][1] * avd.y + acc[i][2] * avd.z + acc[i][3] * avd.w;
#pragma unroll
            for (int o = 1; o < HL; o <<= 1) {
                ps += __shfl_xor_sync(0xffffffffu, ps, o);
                pd += __shfl_xor_sync(0xffffffffu, pd, o);
            }
            float ps1 = __shfl_sync(0xffffffffu, ps, lane + HL);
            float pd1 = __shfl_sync(0xffffffffu, pd, lane + HL);
            if (tj == 0) {
                ((float2*)a_src)[r] = make_float2(ps, ps1);
                ((float2*)a_dst)[r] = make_float2(pd, pd1);
            }
        }
    }
}

// ---------------- fused GAT layer: single-sweep online softmax-aggregate -----
// One warp per destination node. No max subtraction (logits are O(1)).
template <int HC, int LAYER>
__global__ void gat_fused_kernel(const float* __restrict__ bias,
                                 float* __restrict__ out, int n) {
    const float* asrc = (LAYER == 0) ? g_asrc1 : g_asrc2;
    const float* adst = (LAYER == 0) ? g_adst1 : g_adst2;
    const float* h    = (LAYER == 0) ? (const float*)g_h1 : (const float*)g_h2;

    const int d    = (blockIdx.x * blockDim.x + threadIdx.x) >> 5;
    const int lane = threadIdx.x & 31;
    if (d >= n) return;

    const int p0 = g_ptr[d], p1 = g_ptr[d + 1];
    const float2 ad    = ((const float2*)adst)[d];
    const float2 aself = ((const float2*)asrc)[d];

    const bool  h0lane = (lane < 16);
    const float adH = h0lane ? ad.x : ad.y;

    if (HC == 128) {
        // self contribution
        float wgt = __expf(lrelu((h0lane ? aself.x : aself.y) + adH));
        float4 hv = *(const float4*)&h[(size_t)d * 128 + lane * 4];
        float4 acc = make_float4(wgt * hv.x, wgt * hv.y, wgt * hv.z, wgt * hv.w);
        float ssum = wgt;
#pragma unroll 2
        for (int i = p0; i < p1; i++) {
            int s = g_csr[i];
            const float2 as = ((const float2*)asrc)[s];
            float w = __expf(lrelu((h0lane ? as.x : as.y) + adH));
            hv = *(const float4*)&h[(size_t)s * 128 + lane * 4];
            acc.x += w * hv.x; acc.y += w * hv.y;
            acc.z += w * hv.z; acc.w += w * hv.w;
            ssum += w;
        }
        float inv = 1.f / (ssum + 1e-16f);
        float4 b = *(const float4*)&bias[lane * 4];
        acc.x = fmaxf(acc.x * inv + b.x, 0.f);
        acc.y = fmaxf(acc.y * inv + b.y, 0.f);
        acc.z = fmaxf(acc.z * inv + b.z, 0.f);
        acc.w = fmaxf(acc.w * inv + b.w, 0.f);
        *(float4*)&g_agg1[(size_t)d * 128 + lane * 4] = acc;
    } else {
        float wgt = __expf(lrelu((h0lane ? aself.x : aself.y) + adH));
        float2 hv = *(const float2*)&h[(size_t)d * 64 + lane * 2];
        float2 acc = make_float2(wgt * hv.x, wgt * hv.y);
        float ssum = wgt;
#pragma unroll 2
        for (int i = p0; i < p1; i++) {
            int s = g_csr[i];
            const float2 as = ((const float2*)asrc)[s];
            float w = __expf(lrelu((h0lane ? as.x : as.y) + adH));
            hv = *(const float2*)&h[(size_t)s * 64 + lane * 2];
            acc.x += w * hv.x; acc.y += w * hv.y;
            ssum += w;
        }
        float inv = 1.f / (ssum + 1e-16f);
        acc.x *= inv; acc.y *= inv;
        // mean over heads: lane L (head0 cols 2L,2L+1) pairs with lane L+16
        float ox = __shfl_xor_sync(0xffffffffu, acc.x, 16);
        float oy = __shfl_xor_sync(0xffffffffu, acc.y, 16);
        if (lane < 16) {
            float2 o;
            o.x = 0.5f * (acc.x + ox) + bias[lane * 2];
            o.y = 0.5f * (acc.y + oy) + bias[lane * 2 + 1];
            *(float2*)&out[(size_t)d * 32 + lane * 2] = o;
        }
    }
}

// ---------------- launch -----------------------------------------------------
extern "C" void kernel_launch(void* const* d_in, const int* in_sizes, int n_in,
                              void* d_out, int out_size) {
    const float* x   = (const float*)d_in[0];
    const int*   ei  = (const int*)d_in[1];
    const float* W1  = (const float*)d_in[2];
    const float* as1 = (const float*)d_in[3];
    const float* ad1 = (const float*)d_in[4];
    const float* b1  = (const float*)d_in[5];
    const float* W2  = (const float*)d_in[6];
    const float* as2 = (const float*)d_in[7];
    const float* ad2 = (const float*)d_in[8];
    const float* b2  = (const float*)d_in[9];
    float*       out = (float*)d_out;

    const int N = in_sizes[0] / 128;
    const int E = in_sizes[1] / 2;

    const int nb_gemm = (N + 63) / 64;
    const int nb_warp = (N * 32 + 255) / 256;

    // Fork a side stream for the CSR build so it overlaps gemm1.
    cudaStream_t s2;
    cudaStreamCreateWithFlags(&s2, cudaStreamNonBlocking);
    cudaEvent_t ev_fork, ev_join;
    cudaEventCreateWithFlags(&ev_fork, cudaEventDisableTiming);
    cudaEventCreateWithFlags(&ev_join, cudaEventDisableTiming);

    cudaEventRecord(ev_fork, 0);
    cudaStreamWaitEvent(s2, ev_fork, 0);

    // CSR build on side stream
    zero_kernel<<<(N + 255) / 256, 256, 0, s2>>>(N);
    count_kernel<<<(E + 255) / 256, 256, 0, s2>>>(ei, E);
    scan_kernel<<<1, 1024, 0, s2>>>(N);
    scatter_kernel<<<(E + 255) / 256, 256, 0, s2>>>(ei, E);
    cudaEventRecord(ev_join, s2);

    // gemm1 (+ attn proj) on main stream, overlapping CSR
    gemm_kernel<128, 0><<<nb_gemm, 256>>>(x, W1, as1, ad1, N);

    cudaStreamWaitEvent(0, ev_join, 0);

    // ===== Layer 1 aggregate -> Layer 2 =====
    gat_fused_kernel<128, 0><<<nb_warp, 256>>>(b1, nullptr, N);
    gemm_kernel<64, 1><<<nb_gemm, 256>>>(nullptr, W2, as2, ad2, N);
    gat_fused_kernel<64, 1><<<nb_warp, 256>>>(b2, out, N);

    cudaEventDestroy(ev_fork);
    cudaEventDestroy(ev_join);
    cudaStreamDestroy(s2);
}